// round 15
// baseline (speedup 1.0000x reference)
#include <cuda_runtime.h>
#include <cuda_fp16.h>

#define NN 200000
#define NE 1000000
#define NG 4096

// ------------------------- scratch (static device globals) -----------------
static __device__ int            g_degi[NN];      // zeroed inside k_scanC (replay-safe)
static __device__ int            g_off[NN + 1];
static __device__ unsigned short g_rank[NE];      // edge's within-dst rank (from k_deg)
static __device__ int            g_csrc[NE];
static __device__ int            g_bsum[256];
static __device__ float          g_dis[NN];
static __device__ __half         g_x16h[NN * 16]; // x * dis, padded to 16 (fp16, 32B rows)
static __device__ __half         g_agg16h[NN * 16]; // layer-1 aggregate * dis (fp16)
static __device__ __half         g_h1h[NN * 64];  // h1 * dis (fp16)
static __device__ float          g_p2[NN];        // (h2 * dis) . w3l  (scalar per node)
static __device__ float          g_pool1[NG];     // zeroed at end of k_final
static __device__ float          g_cnt[NG];       // zeroed at end of k_final
static __device__ float          g_w3l[64];       // W3 @ lin_w
static __device__ float          g_c0;            // b3.lin_w + lin_b

__device__ __forceinline__ void red_add_f32(float* p, float v) {
    asm volatile("red.global.add.f32 [%0], %1;" :: "l"(p), "f"(v) : "memory");
}

// packed f32x2 FMA (Blackwell): acc = a*b + acc
__device__ __forceinline__ void ffma2(float2& acc, float2 a, float2 b) {
    asm("fma.rn.f32x2 %0, %1, %2, %0;"
        : "+l"(*reinterpret_cast<unsigned long long*>(&acc))
        : "l"(*reinterpret_cast<const unsigned long long*>(&a)),
          "l"(*reinterpret_cast<const unsigned long long*>(&b)));
}

// m16n8k16 fp16 MMA, fp32 accum
__device__ __forceinline__ void mma16816(float* d, unsigned a0, unsigned a1,
                                         unsigned a2, unsigned a3,
                                         unsigned b0, unsigned b1) {
    asm volatile(
        "mma.sync.aligned.m16n8k16.row.col.f32.f16.f16.f32 "
        "{%0,%1,%2,%3}, {%4,%5,%6,%7}, {%8,%9}, {%0,%1,%2,%3};"
        : "+f"(d[0]), "+f"(d[1]), "+f"(d[2]), "+f"(d[3])
        : "r"(a0), "r"(a1), "r"(a2), "r"(a3), "r"(b0), "r"(b1));
}

// --------- degree histogram w/ rank stash + (block 0) prep of w3l / c0 ------
__global__ void k_deg(const int* __restrict__ dst, int e,
                      const float* __restrict__ W3, const float* __restrict__ b3,
                      const float* __restrict__ lw, const float* __restrict__ lb) {
    if (blockIdx.x == 0 && threadIdx.x < 64) {
        int t = threadIdx.x;
        float s = 0.0f;
        for (int j = 0; j < 64; j++) s += W3[t * 64 + j] * lw[j];
        g_w3l[t] = s;
        if (t == 0) {
            float c = lb[0];
            for (int j = 0; j < 64; j++) c += b3[j] * lw[j];
            g_c0 = c;
        }
    }
    int i = (blockIdx.x * 256 + threadIdx.x) * 4;
    if (i + 3 < e) {
        int4 d4 = *(const int4*)&dst[i];
        ushort4 r4;
        r4.x = (unsigned short)atomicAdd(&g_degi[d4.x], 1);
        r4.y = (unsigned short)atomicAdd(&g_degi[d4.y], 1);
        r4.z = (unsigned short)atomicAdd(&g_degi[d4.z], 1);
        r4.w = (unsigned short)atomicAdd(&g_degi[d4.w], 1);
        *(ushort4*)&g_rank[i] = r4;
    } else {
        for (; i < e; i++)
            g_rank[i] = (unsigned short)atomicAdd(&g_degi[dst[i]], 1);
    }
}

// -------- scanA: per-1024-chunk degree sums ----------------------------------
__global__ void k_scanA(int n) {
    __shared__ int ws[8];
    int b = blockIdx.x, t = threadIdx.x;
    int base = b * 1024;
    int sum = 0;
    for (int i = t; i < 1024; i += 256) {
        int g = base + i;
        if (g < n) sum += g_degi[g];
    }
#pragma unroll
    for (int o = 16; o; o >>= 1) sum += __shfl_down_sync(~0u, sum, o);
    if ((t & 31) == 0) ws[t >> 5] = sum;
    __syncthreads();
    if (t == 0) {
        int s = 0;
#pragma unroll
        for (int w = 0; w < 8; w++) s += ws[w];
        g_bsum[b] = s;
    }
}

// -------- scanC: offsets + dis + graph counts --------------------------------
__global__ void k_scanC(const int* __restrict__ batch, int n) {
    __shared__ int ws[8];
    __shared__ int s_boff;
    int b = blockIdx.x, t = threadIdx.x;

    {   // block offset = prefix of chunk sums
        int p = (t < b) ? g_bsum[t] : 0;
#pragma unroll
        for (int o = 16; o; o >>= 1) p += __shfl_down_sync(~0u, p, o);
        if ((t & 31) == 0) ws[t >> 5] = p;
        __syncthreads();
        if (t == 0) {
            int s = 0;
#pragma unroll
            for (int w = 0; w < 8; w++) s += ws[w];
            s_boff = s;
        }
        __syncthreads();
    }

    int base = b * 1024 + t * 4;
    int d[4];
#pragma unroll
    for (int i = 0; i < 4; i++) {
        int g = base + i;
        d[i] = (g < n) ? g_degi[g] : 0;
        if (g < n) g_degi[g] = 0;  // reset for next replay
    }
    int tot = d[0] + d[1] + d[2] + d[3];
    int inc = tot;
#pragma unroll
    for (int o = 1; o < 32; o <<= 1) {
        int u = __shfl_up_sync(~0u, inc, o);
        if ((t & 31) >= o) inc += u;
    }
    if ((t & 31) == 31) ws[t >> 5] = inc;
    __syncthreads();
    if (t < 8) {
        int w = ws[t];
#pragma unroll
        for (int o = 1; o < 8; o <<= 1) {
            int u = __shfl_up_sync(0xFFu, w, o);
            if (t >= o) w += u;
        }
        ws[t] = w;
    }
    __syncthreads();
    int off = inc - tot + ((t >= 32) ? ws[(t >> 5) - 1] : 0) + s_boff;

#pragma unroll
    for (int i = 0; i < 4; i++) {
        int g = base + i;
        if (g < n) {
            g_off[g] = off;
            g_dis[g] = rsqrtf((float)(d[i] + 1));
            if (g == n - 1) g_off[n] = off + d[i];
            off += d[i];
        }
    }
    // graph node counts (dedup across 4 consecutive batch-sorted nodes)
    int cb = -1; float cc = 0.0f;
#pragma unroll
    for (int i = 0; i < 4; i++) {
        int g = base + i;
        if (g >= n) continue;
        int bb = batch[g];
        if (bb == cb) cc += 1.0f;
        else {
            if (cb >= 0) atomicAdd(&g_cnt[cb], cc);
            cb = bb; cc = 1.0f;
        }
    }
    if (cb >= 0) atomicAdd(&g_cnt[cb], cc);
}

// --------- fused: x staging (fp16, coalesced) + CSR fill (4 edges/thread) ----
__global__ void __launch_bounds__(256)
k_stage_fill(const float* __restrict__ x, const int* __restrict__ src,
             const int* __restrict__ dst, int n, int e, int sb) {
    int t = threadIdx.x;
    if ((int)blockIdx.x < sb) {
        __shared__ float xs[128 * 11];
        int nbase = blockIdx.x * 128;
        int lim = min(128, n - nbase) * 11;
        for (int i = t; i < lim; i += 256) xs[i] = x[nbase * 11 + i];
        __syncthreads();
        {   // 128 nodes * 2 chunks (8 halves / 16B each), dis-scaled, zero-pad
            int m = t >> 1, q = t & 1;
            int g = nbase + m;
            if (g < n) {
                float dis = g_dis[g];
                __half2 h[4];
#pragma unroll
                for (int j = 0; j < 4; j++) {
                    int c = q * 8 + j * 2;
                    float a  = (c < 11)     ? xs[m * 11 + c] * dis     : 0.0f;
                    float bb = (c + 1 < 11) ? xs[m * 11 + c + 1] * dis : 0.0f;
                    h[j] = __floats2half2_rn(a, bb);
                }
                *(uint4*)&g_x16h[g * 16 + q * 8] = *(uint4*)h;
            }
        }
    } else {
        // atomic-free fill: slot = off[dst] + stashed rank
        int i = ((blockIdx.x - sb) * 256 + t) * 4;
        if (i + 3 < e) {
            int4 s4 = *(const int4*)&src[i];
            int4 d4 = *(const int4*)&dst[i];
            ushort4 r4 = *(const ushort4*)&g_rank[i];
            g_csrc[g_off[d4.x] + r4.x] = s4.x;
            g_csrc[g_off[d4.y] + r4.y] = s4.y;
            g_csrc[g_off[d4.z] + r4.z] = s4.z;
            g_csrc[g_off[d4.w] + r4.w] = s4.w;
        } else {
            for (; i < e; i++)
                g_csrc[g_off[dst[i]] + g_rank[i]] = src[i];
        }
    }
}

// -- layer 1 pull (standalone, high-occupancy): fp16, 4-edge MLP rounds -------
__global__ void __launch_bounds__(256)
k_pull1(int n) {
    const int t = threadIdx.x;
    const int base = blockIdx.x * 128;
    int lane = t & 1, slot = t >> 1;
    int node = base + slot;
    unsigned gmask = 0x3u << ((t & 31) & ~1);  // this node's 2-lane group
    if (node >= n) return;
    uint4 selfr = *(const uint4*)&g_x16h[node * 16 + lane * 8];
    __half2 acc[4];
    __half2* sp = (__half2*)&selfr;
#pragma unroll
    for (int q = 0; q < 4; q++) acc[q] = sp[q];
    int s0 = g_off[node], s1 = g_off[node + 1];
    int bk = s0;
    for (; bk + 3 < s1; bk += 4) {     // 4-edge rounds, MLP 4
        int ia = g_csrc[bk + lane];
        int ib = g_csrc[bk + 2 + lane];
        int a0 = __shfl_sync(gmask, ia, 0, 2);
        int a1 = __shfl_sync(gmask, ia, 1, 2);
        int a2 = __shfl_sync(gmask, ib, 0, 2);
        int a3 = __shfl_sync(gmask, ib, 1, 2);
        uint4 r0 = *(const uint4*)&g_x16h[a0 * 16 + lane * 8];
        uint4 r1 = *(const uint4*)&g_x16h[a1 * 16 + lane * 8];
        uint4 r2 = *(const uint4*)&g_x16h[a2 * 16 + lane * 8];
        uint4 r3 = *(const uint4*)&g_x16h[a3 * 16 + lane * 8];
        __half2* p0 = (__half2*)&r0;
        __half2* p1 = (__half2*)&r1;
        __half2* p2 = (__half2*)&r2;
        __half2* p3 = (__half2*)&r3;
#pragma unroll
        for (int p = 0; p < 4; p++) {
            __half2 u = __hadd2(p0[p], p1[p]);
            __half2 v = __hadd2(p2[p], p3[p]);
            acc[p] = __hadd2(acc[p], __hadd2(u, v));
        }
    }
    for (; bk + 1 < s1; bk += 2) {     // 2-edge round
        int idx = g_csrc[bk + lane];
        int a0 = __shfl_sync(gmask, idx, 0, 2);
        int a1 = __shfl_sync(gmask, idx, 1, 2);
        uint4 r0 = *(const uint4*)&g_x16h[a0 * 16 + lane * 8];
        uint4 r1 = *(const uint4*)&g_x16h[a1 * 16 + lane * 8];
        __half2* p0 = (__half2*)&r0;
        __half2* p1 = (__half2*)&r1;
#pragma unroll
        for (int p = 0; p < 4; p++)
            acc[p] = __hadd2(acc[p], __hadd2(p0[p], p1[p]));
    }
    if (bk < s1) {                     // tail: single edge
        int a = g_csrc[bk];
        uint4 ra = *(const uint4*)&g_x16h[a * 16 + lane * 8];
        __half2* pa = (__half2*)&ra;
#pragma unroll
        for (int p = 0; p < 4; p++) acc[p] = __hadd2(acc[p], pa[p]);
    }
    // scale by dis and store (coalesced 16B per lane)
    float dd = g_dis[node];
    __half2 outh[4];
#pragma unroll
    for (int q = 0; q < 4; q++) {
        float2 f = __half22float2(acc[q]);
        outh[q] = __floats2half2_rn(f.x * dd, f.y * dd);
    }
    *(uint4*)&g_agg16h[node * 16 + lane * 8] = *(uint4*)outh;
}

// -- layer 1 GEMM (standalone): agg16h -> h1~ (fp16), f32x2, K=16 -------------
__global__ void __launch_bounds__(256)
k_gemm1(const float* __restrict__ W, const float* __restrict__ bias, int n) {
    __shared__ float Am[16 * 136];
    __shared__ float Ws[16 * 64];
    __shared__ float Bs[64];
    const int t = threadIdx.x;
    const int base = blockIdx.x * 128;

    for (int i = t; i < 16 * 64; i += 256) Ws[i] = (i < 11 * 64) ? W[i] : 0.0f;
    if (t < 64) Bs[t] = bias[t];

    {   // stage agg16h -> fp32 k-major tile (coalesced uint4 per thread)
        int lane = t & 1, slot = t >> 1;
        int node = base + slot;
        uint4 r = make_uint4(0, 0, 0, 0);
        if (node < n) r = *(const uint4*)&g_agg16h[node * 16 + lane * 8];
        __half2* rp = (__half2*)&r;
#pragma unroll
        for (int q = 0; q < 4; q++) {
            float2 f = __half22float2(rp[q]);
            Am[(lane * 8 + q * 2 + 0) * 136 + slot] = f.x;
            Am[(lane * 8 + q * 2 + 1) * 136 + slot] = f.y;
        }
    }
    __syncthreads();

    // GEMM: 4 nodes x 8 outs per thread, K=16, f32x2
    const int m0 = (t & 31) * 4;
    const int j0 = (t >> 5) * 8;
    float2 acc2[4][4];
#pragma unroll
    for (int i = 0; i < 4; i++)
#pragma unroll
        for (int p = 0; p < 4; p++) acc2[i][p] = make_float2(0.f, 0.f);

#pragma unroll
    for (int k = 0; k < 16; k++) {
        float4 a4 = *(const float4*)&Am[k * 136 + m0];
        float4 w0 = *(const float4*)&Ws[k * 64 + j0];
        float4 w1 = *(const float4*)&Ws[k * 64 + j0 + 4];
        float2 wp[4] = {{w0.x, w0.y}, {w0.z, w0.w}, {w1.x, w1.y}, {w1.z, w1.w}};
        float a[4] = {a4.x, a4.y, a4.z, a4.w};
#pragma unroll
        for (int i = 0; i < 4; i++) {
            float2 ai = make_float2(a[i], a[i]);
#pragma unroll
            for (int p = 0; p < 4; p++) ffma2(acc2[i][p], ai, wp[p]);
        }
    }

#pragma unroll
    for (int i = 0; i < 4; i++) {
        int g = base + m0 + i;
        if (g >= n) continue;
        float dd = g_dis[g];
        float o[8] = {acc2[i][0].x, acc2[i][0].y, acc2[i][1].x, acc2[i][1].y,
                      acc2[i][2].x, acc2[i][2].y, acc2[i][3].x, acc2[i][3].y};
#pragma unroll
        for (int j = 0; j < 8; j++) o[j] = fmaxf(o[j] + Bs[j0 + j], 0.0f) * dd;
        __half2 h[4];
#pragma unroll
        for (int q = 0; q < 4; q++) h[q] = __floats2half2_rn(o[q * 2], o[q * 2 + 1]);
        *(uint4*)&g_h1h[g * 64 + j0] = *(uint4*)h;
    }
}

// -- layer 2: fp16 pull (shfl-shared indices, HADD2, offsets prefetched)
//    + HMMA GEMM -> p2 scalar ------------------------------------------------
__global__ void __launch_bounds__(256)
k_layer2(const float* __restrict__ W, const float* __restrict__ bias, int n) {
    __shared__ __half Amh[128 * 72];   // node-major, stride 72 halves
    __shared__ __half Wt[64 * 72];     // n-major transposed W2 (fp16), stride 72
    __shared__ float  Bs[64];
    __shared__ float  W3s[64];
    const int t = threadIdx.x;
    const int base = blockIdx.x * 128;

    for (int i = t; i < 64 * 64; i += 256) {
        int k = i >> 6, nn2 = i & 63;
        Wt[nn2 * 72 + k] = __float2half(W[i]);
    }
    if (t < 64) { Bs[t] = bias[t]; W3s[t] = g_w3l[t]; }

    {   // pull: 8 lanes/node (16B fp16 each), 4 serial nodes/thread,
        // shfl-shared index rounds; all 4 nodes' offsets prefetched (MLP 4)
        int lane = t & 7, slot = t >> 3;
        unsigned gmask = 0xFFu << ((t & 31) & ~7);  // this node's 8-lane group
        int off0[4], off1[4];
#pragma unroll
        for (int s = 0; s < 4; s++) {
            int node = base + slot + 32 * s;
            if (node < n) { off0[s] = g_off[node]; off1[s] = g_off[node + 1]; }
            else          { off0[s] = 0;           off1[s] = 0; }
        }
#pragma unroll
        for (int s = 0; s < 4; s++) {
            int node = base + slot + 32 * s;
            __half2 acc[4];
#pragma unroll
            for (int q = 0; q < 4; q++) acc[q] = __float2half2_rn(0.0f);
            uint4 selfr = make_uint4(0, 0, 0, 0);
            float dd = 0.0f;
            if (node < n) {
                selfr = *(const uint4*)&g_h1h[node * 64 + lane * 8];
                int s0 = off0[s], s1 = off1[s];
                for (int bk = s0; bk < s1; bk += 8) {
                    int kk = bk + lane;
                    int idx = (kk < s1) ? g_csrc[kk] : -1;
#pragma unroll
                    for (int q = 0; q < 8; q++) {
                        int a = __shfl_sync(gmask, idx, q, 8);
                        if (a >= 0) {
                            uint4 ra = *(const uint4*)&g_h1h[a * 64 + lane * 8];
                            __half2* pa = (__half2*)&ra;
#pragma unroll
                            for (int p = 0; p < 4; p++)
                                acc[p] = __hadd2(acc[p], pa[p]);
                        }
                    }
                }
                dd = g_dis[node];
            }
            int m = slot + 32 * s;
            __half2* sp = (__half2*)&selfr;
#pragma unroll
            for (int q = 0; q < 4; q++) {
                float2 fa = __half22float2(acc[q]);
                float2 fs = __half22float2(sp[q]);
                *(__half2*)&Amh[m * 72 + lane * 8 + q * 2] =
                    __floats2half2_rn((fs.x + fa.x) * dd, (fs.y + fa.y) * dd);
            }
        }
    }
    __syncthreads();

    // tensor-core GEMM: warp w owns m-tile [w*16, w*16+16), all 8 n-tiles, K=64
    const int lane = t & 31, w = t >> 5;
    const int g2 = lane >> 2, qd = lane & 3;
    float d[8][4];
#pragma unroll
    for (int nt = 0; nt < 8; nt++)
#pragma unroll
        for (int q = 0; q < 4; q++) d[nt][q] = 0.0f;

#pragma unroll
    for (int kstep = 0; kstep < 4; kstep++) {
        int kc = qd * 2 + kstep * 16;
        int row = w * 16 + g2;
        unsigned a0 = *(const unsigned*)&Amh[row * 72 + kc];
        unsigned a1 = *(const unsigned*)&Amh[(row + 8) * 72 + kc];
        unsigned a2 = *(const unsigned*)&Amh[row * 72 + kc + 8];
        unsigned a3 = *(const unsigned*)&Amh[(row + 8) * 72 + kc + 8];
#pragma unroll
        for (int nt = 0; nt < 8; nt++) {
            unsigned b0 = *(const unsigned*)&Wt[(nt * 8 + g2) * 72 + kc];
            unsigned b1 = *(const unsigned*)&Wt[(nt * 8 + g2) * 72 + kc + 8];
            mma16816(d[nt], a0, a1, a2, a3, b0, b1);
        }
    }

    // epilogue: bias+relu, dot with w3l, quad-reduce -> p2
    float part0 = 0.0f, part1 = 0.0f;
#pragma unroll
    for (int nt = 0; nt < 8; nt++) {
        int col = nt * 8 + qd * 2;
        float b0 = Bs[col], b1 = Bs[col + 1];
        float w0 = W3s[col], w1 = W3s[col + 1];
        part0 += fmaxf(d[nt][0] + b0, 0.0f) * w0 + fmaxf(d[nt][1] + b1, 0.0f) * w1;
        part1 += fmaxf(d[nt][2] + b0, 0.0f) * w0 + fmaxf(d[nt][3] + b1, 0.0f) * w1;
    }
    part0 += __shfl_xor_sync(~0u, part0, 1);
    part0 += __shfl_xor_sync(~0u, part0, 2);
    part1 += __shfl_xor_sync(~0u, part1, 1);
    part1 += __shfl_xor_sync(~0u, part1, 2);
    if (qd == 0) {
        int node0 = base + w * 16 + g2;
        int node1 = node0 + 8;
        if (node0 < n) g_p2[node0] = part0 * g_dis[node0];
        if (node1 < n) g_p2[node1] = part1 * g_dis[node1];
    }
}

// ------ layer 3: per-node scalar pull of p2 -> red into graph pool ----------
__global__ void __launch_bounds__(256)
k_layer3(const int* __restrict__ batch, int n) {
    int i = blockIdx.x * 256 + threadIdx.x;
    if (i >= n) return;
    float s = g_p2[i];
    int s0 = g_off[i], s1 = g_off[i + 1];
    int k = s0;
    for (; k + 3 < s1; k += 4) {
        float a = g_p2[g_csrc[k]];
        float b = g_p2[g_csrc[k + 1]];
        float c = g_p2[g_csrc[k + 2]];
        float d = g_p2[g_csrc[k + 3]];
        s += (a + b) + (c + d);
    }
    for (; k < s1; k++) s += g_p2[g_csrc[k]];
    red_add_f32(&g_pool1[batch[i]], s * g_dis[i]);
}

// ------------- final: out[g] = pool1/cnt + c0 ; reset state ------------------
__global__ void k_final(float* __restrict__ out, int ng) {
    int i = blockIdx.x * blockDim.x + threadIdx.x;
    if (i < ng) {
        out[i] = g_pool1[i] / fmaxf(g_cnt[i], 1.0f) + g_c0;
        g_pool1[i] = 0.0f;   // reset for next replay
        g_cnt[i] = 0.0f;
    }
}

// ---------------------------------------------------------------------------
extern "C" void kernel_launch(void* const* d_in, const int* in_sizes, int n_in,
                              void* d_out, int out_size) {
    const float* x   = (const float*)d_in[0];
    const int* ei    = (const int*)d_in[1];
    const int* batch = (const int*)d_in[2];
    const float* W1 = (const float*)d_in[3];
    const float* b1 = (const float*)d_in[4];
    const float* W2 = (const float*)d_in[5];
    const float* b2 = (const float*)d_in[6];
    const float* W3 = (const float*)d_in[7];
    const float* b3 = (const float*)d_in[8];
    const float* lw = (const float*)d_in[9];
    const float* lb = (const float*)d_in[10];
    float* out = (float*)d_out;

    int n  = in_sizes[0] / 11;
    int e  = in_sizes[1] / 2;
    int ng = out_size;
    const int* src = ei;
    const int* dst = ei + e;

    int nb  = (n + 1023) / 1024;
    int sb  = (n + 127) / 128;          // staging blocks
    int fb4 = (e + 1023) / 1024;        // deg/fill blocks (4 edges/thread)

    k_deg<<<fb4, 256>>>(dst, e, W3, b3, lw, lb);
    k_scanA<<<nb, 256>>>(n);
    k_scanC<<<nb, 256>>>(batch, n);
    k_stage_fill<<<sb + fb4, 256>>>(x, src, dst, n, e, sb);

    k_pull1<<<(n + 127) / 128, 256>>>(n);
    k_gemm1<<<(n + 127) / 128, 256>>>(W1, b1, n);
    k_layer2<<<(n + 127) / 128, 256>>>(W2, b2, n);
    k_layer3<<<(n + 255) / 256, 256>>>(batch, n);
    k_final<<<(ng + 255) / 256, 256>>>(out, ng);
}

// round 16
// speedup vs baseline: 1.0003x; 1.0003x over previous
#include <cuda_runtime.h>
#include <cuda_fp16.h>

#define NN 200000
#define NE 1000000
#define NG 4096

// ------------------------- scratch (static device globals) -----------------
static __device__ int            g_degi[NN];      // zeroed inside k_scanC (replay-safe)
static __device__ int            g_off[NN + 1];
static __device__ unsigned short g_rank[NE];      // edge's within-dst rank (from k_deg)
static __device__ int            g_csrc[NE];
static __device__ int            g_bsum[256];
static __device__ float          g_dis[NN];
static __device__ __half         g_x16h[NN * 16]; // x * dis, padded to 16 (fp16, 32B rows)
static __device__ __half         g_h1h[NN * 64];  // h1 * dis (fp16)
static __device__ float          g_p2[NN];        // (h2 * dis) . w3l  (scalar per node)
static __device__ float          g_pool1[NG];     // zeroed at end of k_final
static __device__ float          g_cnt[NG];       // zeroed at end of k_final
static __device__ float          g_w3l[64];       // W3 @ lin_w
static __device__ float          g_c0;            // b3.lin_w + lin_b

__device__ __forceinline__ void red_add_f32(float* p, float v) {
    asm volatile("red.global.add.f32 [%0], %1;" :: "l"(p), "f"(v) : "memory");
}

// packed f32x2 FMA (Blackwell): acc = a*b + acc
__device__ __forceinline__ void ffma2(float2& acc, float2 a, float2 b) {
    asm("fma.rn.f32x2 %0, %1, %2, %0;"
        : "+l"(*reinterpret_cast<unsigned long long*>(&acc))
        : "l"(*reinterpret_cast<const unsigned long long*>(&a)),
          "l"(*reinterpret_cast<const unsigned long long*>(&b)));
}

// m16n8k16 fp16 MMA, fp32 accum
__device__ __forceinline__ void mma16816(float* d, unsigned a0, unsigned a1,
                                         unsigned a2, unsigned a3,
                                         unsigned b0, unsigned b1) {
    asm volatile(
        "mma.sync.aligned.m16n8k16.row.col.f32.f16.f16.f32 "
        "{%0,%1,%2,%3}, {%4,%5,%6,%7}, {%8,%9}, {%0,%1,%2,%3};"
        : "+f"(d[0]), "+f"(d[1]), "+f"(d[2]), "+f"(d[3])
        : "r"(a0), "r"(a1), "r"(a2), "r"(a3), "r"(b0), "r"(b1));
}

// --------- degree histogram w/ rank stash + (block 0) prep of w3l / c0 ------
__global__ void k_deg(const int* __restrict__ dst, int e,
                      const float* __restrict__ W3, const float* __restrict__ b3,
                      const float* __restrict__ lw, const float* __restrict__ lb) {
    if (blockIdx.x == 0 && threadIdx.x < 64) {
        int t = threadIdx.x;
        float s = 0.0f;
        for (int j = 0; j < 64; j++) s += W3[t * 64 + j] * lw[j];
        g_w3l[t] = s;
        if (t == 0) {
            float c = lb[0];
            for (int j = 0; j < 64; j++) c += b3[j] * lw[j];
            g_c0 = c;
        }
    }
    int i = (blockIdx.x * 256 + threadIdx.x) * 4;
    if (i + 3 < e) {
        int4 d4 = *(const int4*)&dst[i];
        ushort4 r4;
        r4.x = (unsigned short)atomicAdd(&g_degi[d4.x], 1);
        r4.y = (unsigned short)atomicAdd(&g_degi[d4.y], 1);
        r4.z = (unsigned short)atomicAdd(&g_degi[d4.z], 1);
        r4.w = (unsigned short)atomicAdd(&g_degi[d4.w], 1);
        *(ushort4*)&g_rank[i] = r4;
    } else {
        for (; i < e; i++)
            g_rank[i] = (unsigned short)atomicAdd(&g_degi[dst[i]], 1);
    }
}

// -------- scanA: per-1024-chunk degree sums ----------------------------------
__global__ void k_scanA(int n) {
    __shared__ int ws[8];
    int b = blockIdx.x, t = threadIdx.x;
    int base = b * 1024;
    int sum = 0;
    for (int i = t; i < 1024; i += 256) {
        int g = base + i;
        if (g < n) sum += g_degi[g];
    }
#pragma unroll
    for (int o = 16; o; o >>= 1) sum += __shfl_down_sync(~0u, sum, o);
    if ((t & 31) == 0) ws[t >> 5] = sum;
    __syncthreads();
    if (t == 0) {
        int s = 0;
#pragma unroll
        for (int w = 0; w < 8; w++) s += ws[w];
        g_bsum[b] = s;
    }
}

// -------- scanC: offsets + dis + graph counts --------------------------------
__global__ void k_scanC(const int* __restrict__ batch, int n) {
    __shared__ int ws[8];
    __shared__ int s_boff;
    int b = blockIdx.x, t = threadIdx.x;

    {   // block offset = prefix of chunk sums
        int p = (t < b) ? g_bsum[t] : 0;
#pragma unroll
        for (int o = 16; o; o >>= 1) p += __shfl_down_sync(~0u, p, o);
        if ((t & 31) == 0) ws[t >> 5] = p;
        __syncthreads();
        if (t == 0) {
            int s = 0;
#pragma unroll
            for (int w = 0; w < 8; w++) s += ws[w];
            s_boff = s;
        }
        __syncthreads();
    }

    int base = b * 1024 + t * 4;
    int d[4];
#pragma unroll
    for (int i = 0; i < 4; i++) {
        int g = base + i;
        d[i] = (g < n) ? g_degi[g] : 0;
        if (g < n) g_degi[g] = 0;  // reset for next replay
    }
    int tot = d[0] + d[1] + d[2] + d[3];
    int inc = tot;
#pragma unroll
    for (int o = 1; o < 32; o <<= 1) {
        int u = __shfl_up_sync(~0u, inc, o);
        if ((t & 31) >= o) inc += u;
    }
    if ((t & 31) == 31) ws[t >> 5] = inc;
    __syncthreads();
    if (t < 8) {
        int w = ws[t];
#pragma unroll
        for (int o = 1; o < 8; o <<= 1) {
            int u = __shfl_up_sync(0xFFu, w, o);
            if (t >= o) w += u;
        }
        ws[t] = w;
    }
    __syncthreads();
    int off = inc - tot + ((t >= 32) ? ws[(t >> 5) - 1] : 0) + s_boff;

#pragma unroll
    for (int i = 0; i < 4; i++) {
        int g = base + i;
        if (g < n) {
            g_off[g] = off;
            g_dis[g] = rsqrtf((float)(d[i] + 1));
            if (g == n - 1) g_off[n] = off + d[i];
            off += d[i];
        }
    }
    // graph node counts (dedup across 4 consecutive batch-sorted nodes)
    int cb = -1; float cc = 0.0f;
#pragma unroll
    for (int i = 0; i < 4; i++) {
        int g = base + i;
        if (g >= n) continue;
        int bb = batch[g];
        if (bb == cb) cc += 1.0f;
        else {
            if (cb >= 0) atomicAdd(&g_cnt[cb], cc);
            cb = bb; cc = 1.0f;
        }
    }
    if (cb >= 0) atomicAdd(&g_cnt[cb], cc);
}

// --------- fused: x staging (fp16, coalesced) + CSR fill (4 edges/thread) ----
__global__ void __launch_bounds__(256)
k_stage_fill(const float* __restrict__ x, const int* __restrict__ src,
             const int* __restrict__ dst, int n, int e, int sb) {
    int t = threadIdx.x;
    if ((int)blockIdx.x < sb) {
        __shared__ float xs[128 * 11];
        int nbase = blockIdx.x * 128;
        int lim = min(128, n - nbase) * 11;
        for (int i = t; i < lim; i += 256) xs[i] = x[nbase * 11 + i];
        __syncthreads();
        {   // 128 nodes * 2 chunks (8 halves / 16B each), dis-scaled, zero-pad
            int m = t >> 1, q = t & 1;
            int g = nbase + m;
            if (g < n) {
                float dis = g_dis[g];
                __half2 h[4];
#pragma unroll
                for (int j = 0; j < 4; j++) {
                    int c = q * 8 + j * 2;
                    float a  = (c < 11)     ? xs[m * 11 + c] * dis     : 0.0f;
                    float bb = (c + 1 < 11) ? xs[m * 11 + c + 1] * dis : 0.0f;
                    h[j] = __floats2half2_rn(a, bb);
                }
                *(uint4*)&g_x16h[g * 16 + q * 8] = *(uint4*)h;
            }
        }
    } else {
        // atomic-free fill: slot = off[dst] + stashed rank
        int i = ((blockIdx.x - sb) * 256 + t) * 4;
        if (i + 3 < e) {
            int4 s4 = *(const int4*)&src[i];
            int4 d4 = *(const int4*)&dst[i];
            ushort4 r4 = *(const ushort4*)&g_rank[i];
            g_csrc[g_off[d4.x] + r4.x] = s4.x;
            g_csrc[g_off[d4.y] + r4.y] = s4.y;
            g_csrc[g_off[d4.z] + r4.z] = s4.z;
            g_csrc[g_off[d4.w] + r4.w] = s4.w;
        } else {
            for (; i < e; i++)
                g_csrc[g_off[dst[i]] + g_rank[i]] = src[i];
        }
    }
}

// -- layer 1: fp16 pull, 4 edges in flight per round + f32x2 GEMM -> h1~ ------
// __launch_bounds__(256, 5): cap regs ~48 -> 5 blocks/SM (62% occ vs 50%).
__global__ void __launch_bounds__(256, 5)
k_layer1(const float* __restrict__ W, const float* __restrict__ bias, int n) {
    __shared__ float Am[16 * 136];
    __shared__ float Ws[16 * 64];
    __shared__ float Bs[64];
    const int t = threadIdx.x;
    const int base = blockIdx.x * 128;

    for (int i = t; i < 16 * 64; i += 256) Ws[i] = (i < 11 * 64) ? W[i] : 0.0f;
    if (t < 64) Bs[t] = bias[t];

    {   // pull: 2 lanes/node (uint4 = 8 halves each), 128 nodes/block,
        // 4-edge rounds: 2 index loads + 4 gathers all in flight
        int lane = t & 1, slot = t >> 1;
        int node = base + slot;
        unsigned gmask = 0x3u << ((t & 31) & ~1);  // this node's 2-lane group
        __half2 acc[4];
#pragma unroll
        for (int q = 0; q < 4; q++) acc[q] = __float2half2_rn(0.0f);
        float dd = 0.0f;
        if (node < n) {
            uint4 selfr = *(const uint4*)&g_x16h[node * 16 + lane * 8];
            __half2* sp = (__half2*)&selfr;
#pragma unroll
            for (int q = 0; q < 4; q++) acc[q] = sp[q];
            int s0 = g_off[node], s1 = g_off[node + 1];
            int bk = s0;
            for (; bk + 3 < s1; bk += 4) {     // 4-edge rounds, MLP 4
                int ia = g_csrc[bk + lane];           // edges bk, bk+1
                int ib = g_csrc[bk + 2 + lane];       // edges bk+2, bk+3
                int a0 = __shfl_sync(gmask, ia, 0, 2);
                int a1 = __shfl_sync(gmask, ia, 1, 2);
                int a2 = __shfl_sync(gmask, ib, 0, 2);
                int a3 = __shfl_sync(gmask, ib, 1, 2);
                uint4 r0 = *(const uint4*)&g_x16h[a0 * 16 + lane * 8];
                uint4 r1 = *(const uint4*)&g_x16h[a1 * 16 + lane * 8];
                uint4 r2 = *(const uint4*)&g_x16h[a2 * 16 + lane * 8];
                uint4 r3 = *(const uint4*)&g_x16h[a3 * 16 + lane * 8];
                __half2* p0 = (__half2*)&r0;
                __half2* p1 = (__half2*)&r1;
                __half2* p2 = (__half2*)&r2;
                __half2* p3 = (__half2*)&r3;
#pragma unroll
                for (int p = 0; p < 4; p++) {
                    __half2 u = __hadd2(p0[p], p1[p]);
                    __half2 v = __hadd2(p2[p], p3[p]);
                    acc[p] = __hadd2(acc[p], __hadd2(u, v));
                }
            }
            for (; bk + 1 < s1; bk += 2) {     // 2-edge round
                int idx = g_csrc[bk + lane];
                int a0 = __shfl_sync(gmask, idx, 0, 2);
                int a1 = __shfl_sync(gmask, idx, 1, 2);
                uint4 r0 = *(const uint4*)&g_x16h[a0 * 16 + lane * 8];
                uint4 r1 = *(const uint4*)&g_x16h[a1 * 16 + lane * 8];
                __half2* p0 = (__half2*)&r0;
                __half2* p1 = (__half2*)&r1;
#pragma unroll
                for (int p = 0; p < 4; p++)
                    acc[p] = __hadd2(acc[p], __hadd2(p0[p], p1[p]));
            }
            if (bk < s1) {                     // tail: single edge
                int a = g_csrc[bk];
                uint4 ra = *(const uint4*)&g_x16h[a * 16 + lane * 8];
                __half2* pa = (__half2*)&ra;
#pragma unroll
                for (int p = 0; p < 4; p++) acc[p] = __hadd2(acc[p], pa[p]);
            }
            dd = g_dis[node];
        }
        // stage to fp32 k-major tile (stride 136)
#pragma unroll
        for (int q = 0; q < 4; q++) {
            float2 f = __half22float2(acc[q]);
            Am[(lane * 8 + q * 2 + 0) * 136 + slot] = f.x * dd;
            Am[(lane * 8 + q * 2 + 1) * 136 + slot] = f.y * dd;
        }
    }
    __syncthreads();

    // GEMM: 4 nodes x 8 outs per thread, K=16, f32x2
    const int m0 = (t & 31) * 4;
    const int j0 = (t >> 5) * 8;
    float2 acc2[4][4];
#pragma unroll
    for (int i = 0; i < 4; i++)
#pragma unroll
        for (int p = 0; p < 4; p++) acc2[i][p] = make_float2(0.f, 0.f);

#pragma unroll
    for (int k = 0; k < 16; k++) {
        float4 a4 = *(const float4*)&Am[k * 136 + m0];
        float4 w0 = *(const float4*)&Ws[k * 64 + j0];
        float4 w1 = *(const float4*)&Ws[k * 64 + j0 + 4];
        float2 wp[4] = {{w0.x, w0.y}, {w0.z, w0.w}, {w1.x, w1.y}, {w1.z, w1.w}};
        float a[4] = {a4.x, a4.y, a4.z, a4.w};
#pragma unroll
        for (int i = 0; i < 4; i++) {
            float2 ai = make_float2(a[i], a[i]);
#pragma unroll
            for (int p = 0; p < 4; p++) ffma2(acc2[i][p], ai, wp[p]);
        }
    }

#pragma unroll
    for (int i = 0; i < 4; i++) {
        int g = base + m0 + i;
        if (g >= n) continue;
        float dd = g_dis[g];
        float o[8] = {acc2[i][0].x, acc2[i][0].y, acc2[i][1].x, acc2[i][1].y,
                      acc2[i][2].x, acc2[i][2].y, acc2[i][3].x, acc2[i][3].y};
#pragma unroll
        for (int j = 0; j < 8; j++) o[j] = fmaxf(o[j] + Bs[j0 + j], 0.0f) * dd;
        __half2 h[4];
#pragma unroll
        for (int q = 0; q < 4; q++) h[q] = __floats2half2_rn(o[q * 2], o[q * 2 + 1]);
        *(uint4*)&g_h1h[g * 64 + j0] = *(uint4*)h;
    }
}

// -- layer 2: fp16 pull (shfl-shared indices, HADD2, offsets prefetched)
//    + HMMA GEMM -> p2 scalar ------------------------------------------------
__global__ void __launch_bounds__(256)
k_layer2(const float* __restrict__ W, const float* __restrict__ bias, int n) {
    __shared__ __half Amh[128 * 72];   // node-major, stride 72 halves
    __shared__ __half Wt[64 * 72];     // n-major transposed W2 (fp16), stride 72
    __shared__ float  Bs[64];
    __shared__ float  W3s[64];
    const int t = threadIdx.x;
    const int base = blockIdx.x * 128;

    for (int i = t; i < 64 * 64; i += 256) {
        int k = i >> 6, nn2 = i & 63;
        Wt[nn2 * 72 + k] = __float2half(W[i]);
    }
    if (t < 64) { Bs[t] = bias[t]; W3s[t] = g_w3l[t]; }

    {   // pull: 8 lanes/node (16B fp16 each), 4 serial nodes/thread,
        // shfl-shared index rounds; all 4 nodes' offsets prefetched (MLP 4)
        int lane = t & 7, slot = t >> 3;
        unsigned gmask = 0xFFu << ((t & 31) & ~7);  // this node's 8-lane group
        int off0[4], off1[4];
#pragma unroll
        for (int s = 0; s < 4; s++) {
            int node = base + slot + 32 * s;
            if (node < n) { off0[s] = g_off[node]; off1[s] = g_off[node + 1]; }
            else          { off0[s] = 0;           off1[s] = 0; }
        }
#pragma unroll
        for (int s = 0; s < 4; s++) {
            int node = base + slot + 32 * s;
            __half2 acc[4];
#pragma unroll
            for (int q = 0; q < 4; q++) acc[q] = __float2half2_rn(0.0f);
            uint4 selfr = make_uint4(0, 0, 0, 0);
            float dd = 0.0f;
            if (node < n) {
                selfr = *(const uint4*)&g_h1h[node * 64 + lane * 8];
                int s0 = off0[s], s1 = off1[s];
                for (int bk = s0; bk < s1; bk += 8) {
                    int kk = bk + lane;
                    int idx = (kk < s1) ? g_csrc[kk] : -1;
#pragma unroll
                    for (int q = 0; q < 8; q++) {
                        int a = __shfl_sync(gmask, idx, q, 8);
                        if (a >= 0) {
                            uint4 ra = *(const uint4*)&g_h1h[a * 64 + lane * 8];
                            __half2* pa = (__half2*)&ra;
#pragma unroll
                            for (int p = 0; p < 4; p++)
                                acc[p] = __hadd2(acc[p], pa[p]);
                        }
                    }
                }
                dd = g_dis[node];
            }
            int m = slot + 32 * s;
            __half2* sp = (__half2*)&selfr;
#pragma unroll
            for (int q = 0; q < 4; q++) {
                float2 fa = __half22float2(acc[q]);
                float2 fs = __half22float2(sp[q]);
                *(__half2*)&Amh[m * 72 + lane * 8 + q * 2] =
                    __floats2half2_rn((fs.x + fa.x) * dd, (fs.y + fa.y) * dd);
            }
        }
    }
    __syncthreads();

    // tensor-core GEMM: warp w owns m-tile [w*16, w*16+16), all 8 n-tiles, K=64
    const int lane = t & 31, w = t >> 5;
    const int g2 = lane >> 2, qd = lane & 3;
    float d[8][4];
#pragma unroll
    for (int nt = 0; nt < 8; nt++)
#pragma unroll
        for (int q = 0; q < 4; q++) d[nt][q] = 0.0f;

#pragma unroll
    for (int kstep = 0; kstep < 4; kstep++) {
        int kc = qd * 2 + kstep * 16;
        int row = w * 16 + g2;
        unsigned a0 = *(const unsigned*)&Amh[row * 72 + kc];
        unsigned a1 = *(const unsigned*)&Amh[(row + 8) * 72 + kc];
        unsigned a2 = *(const unsigned*)&Amh[row * 72 + kc + 8];
        unsigned a3 = *(const unsigned*)&Amh[(row + 8) * 72 + kc + 8];
#pragma unroll
        for (int nt = 0; nt < 8; nt++) {
            unsigned b0 = *(const unsigned*)&Wt[(nt * 8 + g2) * 72 + kc];
            unsigned b1 = *(const unsigned*)&Wt[(nt * 8 + g2) * 72 + kc + 8];
            mma16816(d[nt], a0, a1, a2, a3, b0, b1);
        }
    }

    // epilogue: bias+relu, dot with w3l, quad-reduce -> p2
    float part0 = 0.0f, part1 = 0.0f;
#pragma unroll
    for (int nt = 0; nt < 8; nt++) {
        int col = nt * 8 + qd * 2;
        float b0 = Bs[col], b1 = Bs[col + 1];
        float w0 = W3s[col], w1 = W3s[col + 1];
        part0 += fmaxf(d[nt][0] + b0, 0.0f) * w0 + fmaxf(d[nt][1] + b1, 0.0f) * w1;
        part1 += fmaxf(d[nt][2] + b0, 0.0f) * w0 + fmaxf(d[nt][3] + b1, 0.0f) * w1;
    }
    part0 += __shfl_xor_sync(~0u, part0, 1);
    part0 += __shfl_xor_sync(~0u, part0, 2);
    part1 += __shfl_xor_sync(~0u, part1, 1);
    part1 += __shfl_xor_sync(~0u, part1, 2);
    if (qd == 0) {
        int node0 = base + w * 16 + g2;
        int node1 = node0 + 8;
        if (node0 < n) g_p2[node0] = part0 * g_dis[node0];
        if (node1 < n) g_p2[node1] = part1 * g_dis[node1];
    }
}

// ------ layer 3: per-node scalar pull of p2 -> red into graph pool ----------
__global__ void __launch_bounds__(256)
k_layer3(const int* __restrict__ batch, int n) {
    int i = blockIdx.x * 256 + threadIdx.x;
    if (i >= n) return;
    float s = g_p2[i];
    int s0 = g_off[i], s1 = g_off[i + 1];
    int k = s0;
    for (; k + 3 < s1; k += 4) {
        float a = g_p2[g_csrc[k]];
        float b = g_p2[g_csrc[k + 1]];
        float c = g_p2[g_csrc[k + 2]];
        float d = g_p2[g_csrc[k + 3]];
        s += (a + b) + (c + d);
    }
    for (; k < s1; k++) s += g_p2[g_csrc[k]];
    red_add_f32(&g_pool1[batch[i]], s * g_dis[i]);
}

// ------------- final: out[g] = pool1/cnt + c0 ; reset state ------------------
__global__ void k_final(float* __restrict__ out, int ng) {
    int i = blockIdx.x * blockDim.x + threadIdx.x;
    if (i < ng) {
        out[i] = g_pool1[i] / fmaxf(g_cnt[i], 1.0f) + g_c0;
        g_pool1[i] = 0.0f;   // reset for next replay
        g_cnt[i] = 0.0f;
    }
}

// ---------------------------------------------------------------------------
extern "C" void kernel_launch(void* const* d_in, const int* in_sizes, int n_in,
                              void* d_out, int out_size) {
    const float* x   = (const float*)d_in[0];
    const int* ei    = (const int*)d_in[1];
    const int* batch = (const int*)d_in[2];
    const float* W1 = (const float*)d_in[3];
    const float* b1 = (const float*)d_in[4];
    const float* W2 = (const float*)d_in[5];
    const float* b2 = (const float*)d_in[6];
    const float* W3 = (const float*)d_in[7];
    const float* b3 = (const float*)d_in[8];
    const float* lw = (const float*)d_in[9];
    const float* lb = (const float*)d_in[10];
    float* out = (float*)d_out;

    int n  = in_sizes[0] / 11;
    int e  = in_sizes[1] / 2;
    int ng = out_size;
    const int* src = ei;
    const int* dst = ei + e;

    int nb  = (n + 1023) / 1024;
    int sb  = (n + 127) / 128;          // staging blocks
    int fb4 = (e + 1023) / 1024;        // deg/fill blocks (4 edges/thread)

    k_deg<<<fb4, 256>>>(dst, e, W3, b3, lw, lb);
    k_scanA<<<nb, 256>>>(n);
    k_scanC<<<nb, 256>>>(batch, n);
    k_stage_fill<<<sb + fb4, 256>>>(x, src, dst, n, e, sb);

    k_layer1<<<(n + 127) / 128, 256>>>(W1, b1, n);
    k_layer2<<<(n + 127) / 128, 256>>>(W2, b2, n);
    k_layer3<<<(n + 255) / 256, 256>>>(batch, n);
    k_final<<<(ng + 255) / 256, 256>>>(out, ng);
}

// round 17
// speedup vs baseline: 1.0183x; 1.0180x over previous
#include <cuda_runtime.h>
#include <cuda_fp16.h>

#define NN 200000
#define NE 1000000
#define NG 4096

// ------------------------- scratch (static device globals) -----------------
static __device__ int            g_degi[NN];      // zeroed inside k_scanC (replay-safe)
static __device__ int            g_off[NN + 1];
static __device__ unsigned short g_rank[NE];      // edge's within-dst rank (from k_deg)
static __device__ int            g_csrc[NE];
static __device__ int            g_bsum[256];
static __device__ float          g_dis[NN];
static __device__ __half         g_x16h[NN * 16]; // x * dis, padded to 16 (fp16, 32B rows)
static __device__ __half         g_h1h[NN * 64];  // h1 * dis (fp16)
static __device__ float          g_p2[NN];        // (h2 * dis) . w3l  (scalar per node)
static __device__ float          g_pool1[NG];     // zeroed at end of k_final
static __device__ float          g_cnt[NG];       // zeroed at end of k_final
static __device__ float          g_w3l[64];       // W3 @ lin_w
static __device__ float          g_c0;            // b3.lin_w + lin_b

__device__ __forceinline__ void red_add_f32(float* p, float v) {
    asm volatile("red.global.add.f32 [%0], %1;" :: "l"(p), "f"(v) : "memory");
}

// packed f32x2 FMA (Blackwell): acc = a*b + acc
__device__ __forceinline__ void ffma2(float2& acc, float2 a, float2 b) {
    asm("fma.rn.f32x2 %0, %1, %2, %0;"
        : "+l"(*reinterpret_cast<unsigned long long*>(&acc))
        : "l"(*reinterpret_cast<const unsigned long long*>(&a)),
          "l"(*reinterpret_cast<const unsigned long long*>(&b)));
}

// m16n8k16 fp16 MMA, fp32 accum
__device__ __forceinline__ void mma16816(float* d, unsigned a0, unsigned a1,
                                         unsigned a2, unsigned a3,
                                         unsigned b0, unsigned b1) {
    asm volatile(
        "mma.sync.aligned.m16n8k16.row.col.f32.f16.f16.f32 "
        "{%0,%1,%2,%3}, {%4,%5,%6,%7}, {%8,%9}, {%0,%1,%2,%3};"
        : "+f"(d[0]), "+f"(d[1]), "+f"(d[2]), "+f"(d[3])
        : "r"(a0), "r"(a1), "r"(a2), "r"(a3), "r"(b0), "r"(b1));
}

// --------- degree histogram w/ rank stash + (block 0) prep of w3l / c0 ------
__global__ void k_deg(const int* __restrict__ dst, int e,
                      const float* __restrict__ W3, const float* __restrict__ b3,
                      const float* __restrict__ lw, const float* __restrict__ lb) {
    if (blockIdx.x == 0 && threadIdx.x < 64) {
        int t = threadIdx.x;
        float s = 0.0f;
        for (int j = 0; j < 64; j++) s += W3[t * 64 + j] * lw[j];
        g_w3l[t] = s;
        if (t == 0) {
            float c = lb[0];
            for (int j = 0; j < 64; j++) c += b3[j] * lw[j];
            g_c0 = c;
        }
    }
    int i = (blockIdx.x * 256 + threadIdx.x) * 4;
    if (i + 3 < e) {
        int4 d4 = *(const int4*)&dst[i];
        ushort4 r4;
        r4.x = (unsigned short)atomicAdd(&g_degi[d4.x], 1);
        r4.y = (unsigned short)atomicAdd(&g_degi[d4.y], 1);
        r4.z = (unsigned short)atomicAdd(&g_degi[d4.z], 1);
        r4.w = (unsigned short)atomicAdd(&g_degi[d4.w], 1);
        *(ushort4*)&g_rank[i] = r4;
    } else {
        for (; i < e; i++)
            g_rank[i] = (unsigned short)atomicAdd(&g_degi[dst[i]], 1);
    }
}

// -------- scanA: per-1024-chunk degree sums ----------------------------------
__global__ void k_scanA(int n) {
    __shared__ int ws[8];
    int b = blockIdx.x, t = threadIdx.x;
    int base = b * 1024;
    int sum = 0;
    for (int i = t; i < 1024; i += 256) {
        int g = base + i;
        if (g < n) sum += g_degi[g];
    }
#pragma unroll
    for (int o = 16; o; o >>= 1) sum += __shfl_down_sync(~0u, sum, o);
    if ((t & 31) == 0) ws[t >> 5] = sum;
    __syncthreads();
    if (t == 0) {
        int s = 0;
#pragma unroll
        for (int w = 0; w < 8; w++) s += ws[w];
        g_bsum[b] = s;
    }
}

// -------- scanC: offsets + dis + graph counts --------------------------------
__global__ void k_scanC(const int* __restrict__ batch, int n) {
    __shared__ int ws[8];
    __shared__ int s_boff;
    int b = blockIdx.x, t = threadIdx.x;

    {   // block offset = prefix of chunk sums
        int p = (t < b) ? g_bsum[t] : 0;
#pragma unroll
        for (int o = 16; o; o >>= 1) p += __shfl_down_sync(~0u, p, o);
        if ((t & 31) == 0) ws[t >> 5] = p;
        __syncthreads();
        if (t == 0) {
            int s = 0;
#pragma unroll
            for (int w = 0; w < 8; w++) s += ws[w];
            s_boff = s;
        }
        __syncthreads();
    }

    int base = b * 1024 + t * 4;
    int d[4];
#pragma unroll
    for (int i = 0; i < 4; i++) {
        int g = base + i;
        d[i] = (g < n) ? g_degi[g] : 0;
        if (g < n) g_degi[g] = 0;  // reset for next replay
    }
    int tot = d[0] + d[1] + d[2] + d[3];
    int inc = tot;
#pragma unroll
    for (int o = 1; o < 32; o <<= 1) {
        int u = __shfl_up_sync(~0u, inc, o);
        if ((t & 31) >= o) inc += u;
    }
    if ((t & 31) == 31) ws[t >> 5] = inc;
    __syncthreads();
    if (t < 8) {
        int w = ws[t];
#pragma unroll
        for (int o = 1; o < 8; o <<= 1) {
            int u = __shfl_up_sync(0xFFu, w, o);
            if (t >= o) w += u;
        }
        ws[t] = w;
    }
    __syncthreads();
    int off = inc - tot + ((t >= 32) ? ws[(t >> 5) - 1] : 0) + s_boff;

#pragma unroll
    for (int i = 0; i < 4; i++) {
        int g = base + i;
        if (g < n) {
            g_off[g] = off;
            g_dis[g] = rsqrtf((float)(d[i] + 1));
            if (g == n - 1) g_off[n] = off + d[i];
            off += d[i];
        }
    }
    // graph node counts (dedup across 4 consecutive batch-sorted nodes)
    int cb = -1; float cc = 0.0f;
#pragma unroll
    for (int i = 0; i < 4; i++) {
        int g = base + i;
        if (g >= n) continue;
        int bb = batch[g];
        if (bb == cb) cc += 1.0f;
        else {
            if (cb >= 0) atomicAdd(&g_cnt[cb], cc);
            cb = bb; cc = 1.0f;
        }
    }
    if (cb >= 0) atomicAdd(&g_cnt[cb], cc);
}

// --------- fused: x staging (fp16, coalesced) + CSR fill (4 edges/thread) ----
__global__ void __launch_bounds__(256)
k_stage_fill(const float* __restrict__ x, const int* __restrict__ src,
             const int* __restrict__ dst, int n, int e, int sb) {
    int t = threadIdx.x;
    if ((int)blockIdx.x < sb) {
        __shared__ float xs[128 * 11];
        int nbase = blockIdx.x * 128;
        int lim = min(128, n - nbase) * 11;
        for (int i = t; i < lim; i += 256) xs[i] = x[nbase * 11 + i];
        __syncthreads();
        {   // 128 nodes * 2 chunks (8 halves / 16B each), dis-scaled, zero-pad
            int m = t >> 1, q = t & 1;
            int g = nbase + m;
            if (g < n) {
                float dis = g_dis[g];
                __half2 h[4];
#pragma unroll
                for (int j = 0; j < 4; j++) {
                    int c = q * 8 + j * 2;
                    float a  = (c < 11)     ? xs[m * 11 + c] * dis     : 0.0f;
                    float bb = (c + 1 < 11) ? xs[m * 11 + c + 1] * dis : 0.0f;
                    h[j] = __floats2half2_rn(a, bb);
                }
                *(uint4*)&g_x16h[g * 16 + q * 8] = *(uint4*)h;
            }
        }
    } else {
        // atomic-free fill: slot = off[dst] + stashed rank
        int i = ((blockIdx.x - sb) * 256 + t) * 4;
        if (i + 3 < e) {
            int4 s4 = *(const int4*)&src[i];
            int4 d4 = *(const int4*)&dst[i];
            ushort4 r4 = *(const ushort4*)&g_rank[i];
            g_csrc[g_off[d4.x] + r4.x] = s4.x;
            g_csrc[g_off[d4.y] + r4.y] = s4.y;
            g_csrc[g_off[d4.z] + r4.z] = s4.z;
            g_csrc[g_off[d4.w] + r4.w] = s4.w;
        } else {
            for (; i < e; i++)
                g_csrc[g_off[dst[i]] + g_rank[i]] = src[i];
        }
    }
}

// -- layer 1: fp16 pull, 4 edges in flight per round + f32x2 GEMM -> h1~ ------
__global__ void __launch_bounds__(256)
k_layer1(const float* __restrict__ W, const float* __restrict__ bias, int n) {
    __shared__ float Am[16 * 136];
    __shared__ float Ws[16 * 64];
    __shared__ float Bs[64];
    const int t = threadIdx.x;
    const int base = blockIdx.x * 128;

    for (int i = t; i < 16 * 64; i += 256) Ws[i] = (i < 11 * 64) ? W[i] : 0.0f;
    if (t < 64) Bs[t] = bias[t];

    {   // pull: 2 lanes/node (uint4 = 8 halves each), 128 nodes/block,
        // 4-edge rounds: 2 index loads + 4 gathers all in flight
        int lane = t & 1, slot = t >> 1;
        int node = base + slot;
        unsigned gmask = 0x3u << ((t & 31) & ~1);  // this node's 2-lane group
        __half2 acc[4];
#pragma unroll
        for (int q = 0; q < 4; q++) acc[q] = __float2half2_rn(0.0f);
        float dd = 0.0f;
        if (node < n) {
            uint4 selfr = *(const uint4*)&g_x16h[node * 16 + lane * 8];
            __half2* sp = (__half2*)&selfr;
#pragma unroll
            for (int q = 0; q < 4; q++) acc[q] = sp[q];
            int s0 = g_off[node], s1 = g_off[node + 1];
            int bk = s0;
            for (; bk + 3 < s1; bk += 4) {     // 4-edge rounds, MLP 4
                int ia = g_csrc[bk + lane];           // edges bk, bk+1
                int ib = g_csrc[bk + 2 + lane];       // edges bk+2, bk+3
                int a0 = __shfl_sync(gmask, ia, 0, 2);
                int a1 = __shfl_sync(gmask, ia, 1, 2);
                int a2 = __shfl_sync(gmask, ib, 0, 2);
                int a3 = __shfl_sync(gmask, ib, 1, 2);
                uint4 r0 = *(const uint4*)&g_x16h[a0 * 16 + lane * 8];
                uint4 r1 = *(const uint4*)&g_x16h[a1 * 16 + lane * 8];
                uint4 r2 = *(const uint4*)&g_x16h[a2 * 16 + lane * 8];
                uint4 r3 = *(const uint4*)&g_x16h[a3 * 16 + lane * 8];
                __half2* p0 = (__half2*)&r0;
                __half2* p1 = (__half2*)&r1;
                __half2* p2 = (__half2*)&r2;
                __half2* p3 = (__half2*)&r3;
#pragma unroll
                for (int p = 0; p < 4; p++) {
                    __half2 u = __hadd2(p0[p], p1[p]);
                    __half2 v = __hadd2(p2[p], p3[p]);
                    acc[p] = __hadd2(acc[p], __hadd2(u, v));
                }
            }
            for (; bk + 1 < s1; bk += 2) {     // 2-edge round
                int idx = g_csrc[bk + lane];
                int a0 = __shfl_sync(gmask, idx, 0, 2);
                int a1 = __shfl_sync(gmask, idx, 1, 2);
                uint4 r0 = *(const uint4*)&g_x16h[a0 * 16 + lane * 8];
                uint4 r1 = *(const uint4*)&g_x16h[a1 * 16 + lane * 8];
                __half2* p0 = (__half2*)&r0;
                __half2* p1 = (__half2*)&r1;
#pragma unroll
                for (int p = 0; p < 4; p++)
                    acc[p] = __hadd2(acc[p], __hadd2(p0[p], p1[p]));
            }
            if (bk < s1) {                     // tail: single edge
                int a = g_csrc[bk];
                uint4 ra = *(const uint4*)&g_x16h[a * 16 + lane * 8];
                __half2* pa = (__half2*)&ra;
#pragma unroll
                for (int p = 0; p < 4; p++) acc[p] = __hadd2(acc[p], pa[p]);
            }
            dd = g_dis[node];
        }
        // stage to fp32 k-major tile (stride 136)
#pragma unroll
        for (int q = 0; q < 4; q++) {
            float2 f = __half22float2(acc[q]);
            Am[(lane * 8 + q * 2 + 0) * 136 + slot] = f.x * dd;
            Am[(lane * 8 + q * 2 + 1) * 136 + slot] = f.y * dd;
        }
    }
    __syncthreads();

    // GEMM: 4 nodes x 8 outs per thread, K=16, f32x2
    const int m0 = (t & 31) * 4;
    const int j0 = (t >> 5) * 8;
    float2 acc2[4][4];
#pragma unroll
    for (int i = 0; i < 4; i++)
#pragma unroll
        for (int p = 0; p < 4; p++) acc2[i][p] = make_float2(0.f, 0.f);

#pragma unroll
    for (int k = 0; k < 16; k++) {
        float4 a4 = *(const float4*)&Am[k * 136 + m0];
        float4 w0 = *(const float4*)&Ws[k * 64 + j0];
        float4 w1 = *(const float4*)&Ws[k * 64 + j0 + 4];
        float2 wp[4] = {{w0.x, w0.y}, {w0.z, w0.w}, {w1.x, w1.y}, {w1.z, w1.w}};
        float a[4] = {a4.x, a4.y, a4.z, a4.w};
#pragma unroll
        for (int i = 0; i < 4; i++) {
            float2 ai = make_float2(a[i], a[i]);
#pragma unroll
            for (int p = 0; p < 4; p++) ffma2(acc2[i][p], ai, wp[p]);
        }
    }

#pragma unroll
    for (int i = 0; i < 4; i++) {
        int g = base + m0 + i;
        if (g >= n) continue;
        float dd = g_dis[g];
        float o[8] = {acc2[i][0].x, acc2[i][0].y, acc2[i][1].x, acc2[i][1].y,
                      acc2[i][2].x, acc2[i][2].y, acc2[i][3].x, acc2[i][3].y};
#pragma unroll
        for (int j = 0; j < 8; j++) o[j] = fmaxf(o[j] + Bs[j0 + j], 0.0f) * dd;
        __half2 h[4];
#pragma unroll
        for (int q = 0; q < 4; q++) h[q] = __floats2half2_rn(o[q * 2], o[q * 2 + 1]);
        *(uint4*)&g_h1h[g * 64 + j0] = *(uint4*)h;
    }
}

// -- layer 2: fp16 pull (shfl-shared indices, HADD2, offsets prefetched)
//    + HMMA GEMM -> p2 scalar ------------------------------------------------
__global__ void __launch_bounds__(256)
k_layer2(const float* __restrict__ W, const float* __restrict__ bias, int n) {
    __shared__ __half Amh[128 * 72];   // node-major, stride 72 halves
    __shared__ __half Wt[64 * 72];     // n-major transposed W2 (fp16), stride 72
    __shared__ float  Bs[64];
    __shared__ float  W3s[64];
    const int t = threadIdx.x;
    const int base = blockIdx.x * 128;

    for (int i = t; i < 64 * 64; i += 256) {
        int k = i >> 6, nn2 = i & 63;
        Wt[nn2 * 72 + k] = __float2half(W[i]);
    }
    if (t < 64) { Bs[t] = bias[t]; W3s[t] = g_w3l[t]; }

    {   // pull: 8 lanes/node (16B fp16 each), 4 serial nodes/thread,
        // shfl-shared index rounds; all 4 nodes' offsets prefetched (MLP 4)
        int lane = t & 7, slot = t >> 3;
        unsigned gmask = 0xFFu << ((t & 31) & ~7);  // this node's 8-lane group
        int off0[4], off1[4];
#pragma unroll
        for (int s = 0; s < 4; s++) {
            int node = base + slot + 32 * s;
            if (node < n) { off0[s] = g_off[node]; off1[s] = g_off[node + 1]; }
            else          { off0[s] = 0;           off1[s] = 0; }
        }
#pragma unroll
        for (int s = 0; s < 4; s++) {
            int node = base + slot + 32 * s;
            __half2 acc[4];
#pragma unroll
            for (int q = 0; q < 4; q++) acc[q] = __float2half2_rn(0.0f);
            uint4 selfr = make_uint4(0, 0, 0, 0);
            float dd = 0.0f;
            if (node < n) {
                selfr = *(const uint4*)&g_h1h[node * 64 + lane * 8];
                int s0 = off0[s], s1 = off1[s];
                for (int bk = s0; bk < s1; bk += 8) {
                    int kk = bk + lane;
                    int idx = (kk < s1) ? g_csrc[kk] : -1;
#pragma unroll
                    for (int q = 0; q < 8; q++) {
                        int a = __shfl_sync(gmask, idx, q, 8);
                        if (a >= 0) {
                            uint4 ra = *(const uint4*)&g_h1h[a * 64 + lane * 8];
                            __half2* pa = (__half2*)&ra;
#pragma unroll
                            for (int p = 0; p < 4; p++)
                                acc[p] = __hadd2(acc[p], pa[p]);
                        }
                    }
                }
                dd = g_dis[node];
            }
            int m = slot + 32 * s;
            __half2* sp = (__half2*)&selfr;
#pragma unroll
            for (int q = 0; q < 4; q++) {
                float2 fa = __half22float2(acc[q]);
                float2 fs = __half22float2(sp[q]);
                *(__half2*)&Amh[m * 72 + lane * 8 + q * 2] =
                    __floats2half2_rn((fs.x + fa.x) * dd, (fs.y + fa.y) * dd);
            }
        }
    }
    __syncthreads();

    // tensor-core GEMM: warp w owns m-tile [w*16, w*16+16), all 8 n-tiles, K=64
    const int lane = t & 31, w = t >> 5;
    const int g2 = lane >> 2, qd = lane & 3;
    float d[8][4];
#pragma unroll
    for (int nt = 0; nt < 8; nt++)
#pragma unroll
        for (int q = 0; q < 4; q++) d[nt][q] = 0.0f;

#pragma unroll
    for (int kstep = 0; kstep < 4; kstep++) {
        int kc = qd * 2 + kstep * 16;
        int row = w * 16 + g2;
        unsigned a0 = *(const unsigned*)&Amh[row * 72 + kc];
        unsigned a1 = *(const unsigned*)&Amh[(row + 8) * 72 + kc];
        unsigned a2 = *(const unsigned*)&Amh[row * 72 + kc + 8];
        unsigned a3 = *(const unsigned*)&Amh[(row + 8) * 72 + kc + 8];
#pragma unroll
        for (int nt = 0; nt < 8; nt++) {
            unsigned b0 = *(const unsigned*)&Wt[(nt * 8 + g2) * 72 + kc];
            unsigned b1 = *(const unsigned*)&Wt[(nt * 8 + g2) * 72 + kc + 8];
            mma16816(d[nt], a0, a1, a2, a3, b0, b1);
        }
    }

    // epilogue: bias+relu, dot with w3l, quad-reduce -> p2
    float part0 = 0.0f, part1 = 0.0f;
#pragma unroll
    for (int nt = 0; nt < 8; nt++) {
        int col = nt * 8 + qd * 2;
        float b0 = Bs[col], b1 = Bs[col + 1];
        float w0 = W3s[col], w1 = W3s[col + 1];
        part0 += fmaxf(d[nt][0] + b0, 0.0f) * w0 + fmaxf(d[nt][1] + b1, 0.0f) * w1;
        part1 += fmaxf(d[nt][2] + b0, 0.0f) * w0 + fmaxf(d[nt][3] + b1, 0.0f) * w1;
    }
    part0 += __shfl_xor_sync(~0u, part0, 1);
    part0 += __shfl_xor_sync(~0u, part0, 2);
    part1 += __shfl_xor_sync(~0u, part1, 1);
    part1 += __shfl_xor_sync(~0u, part1, 2);
    if (qd == 0) {
        int node0 = base + w * 16 + g2;
        int node1 = node0 + 8;
        if (node0 < n) g_p2[node0] = part0 * g_dis[node0];
        if (node1 < n) g_p2[node1] = part1 * g_dis[node1];
    }
}

// ------ layer 3: per-node scalar pull of p2 -> red into graph pool ----------
__global__ void __launch_bounds__(256)
k_layer3(const int* __restrict__ batch, int n) {
    int i = blockIdx.x * 256 + threadIdx.x;
    if (i >= n) return;
    float s = g_p2[i];
    int s0 = g_off[i], s1 = g_off[i + 1];
    int k = s0;
    for (; k + 3 < s1; k += 4) {
        float a = g_p2[g_csrc[k]];
        float b = g_p2[g_csrc[k + 1]];
        float c = g_p2[g_csrc[k + 2]];
        float d = g_p2[g_csrc[k + 3]];
        s += (a + b) + (c + d);
    }
    for (; k < s1; k++) s += g_p2[g_csrc[k]];
    red_add_f32(&g_pool1[batch[i]], s * g_dis[i]);
}

// ------------- final: out[g] = pool1/cnt + c0 ; reset state ------------------
__global__ void k_final(float* __restrict__ out, int ng) {
    int i = blockIdx.x * blockDim.x + threadIdx.x;
    if (i < ng) {
        out[i] = g_pool1[i] / fmaxf(g_cnt[i], 1.0f) + g_c0;
        g_pool1[i] = 0.0f;   // reset for next replay
        g_cnt[i] = 0.0f;
    }
}

// ---------------------------------------------------------------------------
extern "C" void kernel_launch(void* const* d_in, const int* in_sizes, int n_in,
                              void* d_out, int out_size) {
    const float* x   = (const float*)d_in[0];
    const int* ei    = (const int*)d_in[1];
    const int* batch = (const int*)d_in[2];
    const float* W1 = (const float*)d_in[3];
    const float* b1 = (const float*)d_in[4];
    const float* W2 = (const float*)d_in[5];
    const float* b2 = (const float*)d_in[6];
    const float* W3 = (const float*)d_in[7];
    const float* b3 = (const float*)d_in[8];
    const float* lw = (const float*)d_in[9];
    const float* lb = (const float*)d_in[10];
    float* out = (float*)d_out;

    int n  = in_sizes[0] / 11;
    int e  = in_sizes[1] / 2;
    int ng = out_size;
    const int* src = ei;
    const int* dst = ei + e;

    int nb  = (n + 1023) / 1024;
    int sb  = (n + 127) / 128;          // staging blocks
    int fb4 = (e + 1023) / 1024;        // deg/fill blocks (4 edges/thread)

    k_deg<<<fb4, 256>>>(dst, e, W3, b3, lw, lb);
    k_scanA<<<nb, 256>>>(n);
    k_scanC<<<nb, 256>>>(batch, n);
    k_stage_fill<<<sb + fb4, 256>>>(x, src, dst, n, e, sb);

    k_layer1<<<(n + 127) / 128, 256>>>(W1, b1, n);
    k_layer2<<<(n + 127) / 128, 256>>>(W2, b2, n);
    k_layer3<<<(n + 255) / 256, 256>>>(batch, n);
    k_final<<<(ng + 255) / 256, 256>>>(out, ng);
}